// round 7
// baseline (speedup 1.0000x reference)
#include <cuda_runtime.h>
#include <cstdint>

// ---------------------------------------------------------------------------
// Problem constants
// ---------------------------------------------------------------------------
#define L_NUM 2
#define HS    512
#define BB    64
#define SS    1024
#define INW   512
#define ROWS  1024            // 2 gates * HS, interleaved: r = 2*h + g' (g': 0=z, 1=n)
#define NCTA  128             // persistent step CTAs (<=148 SMs -> co-resident)
#define SEQ_ELEMS (BB*SS*HS)  // 33,554,432

// ---------------------------------------------------------------------------
// Device scratch (static __device__ arrays: the allowed scratch mechanism)
// ---------------------------------------------------------------------------
__device__ __align__(16) float g_WG  [L_NUM*ROWS*INW];             // 4 MB  [l][r][i]
__device__ __align__(16) float g_UG  [L_NUM*ROWS*HS];              // 4 MB  [l][r][o]
__device__ __align__(16) float g_bias[L_NUM*ROWS];                 // [l][r]
__device__ __align__(16) float g_Gx  [(size_t)SS*L_NUM*ROWS*BB];   // 512 MB [t][l][r][b]
__device__ __align__(16) float g_Hbuf[2*L_NUM*HS*BB];              // ping-pong [p][l][h][b]
__device__ unsigned long long g_arrive;                            // grid barrier counter

// ---------------------------------------------------------------------------
// Kernel A: combined weights + biases.
//   WG[l][2h+g'][i] = W1[l,g'+1]*W2[l,h,i] + dW1[l,g'+1]*dW2[l,h,i]
//   UG analogous with U.  bias[l][2h+g'] = (b1+b2)[l, (g'+1)*HS + h]
// ---------------------------------------------------------------------------
__global__ void combine_kernel(const float* __restrict__ W1, const float* __restrict__ W2,
                               const float* __restrict__ U1, const float* __restrict__ U2,
                               const float* __restrict__ dW1, const float* __restrict__ dW2,
                               const float* __restrict__ dU1, const float* __restrict__ dU2,
                               const float* __restrict__ b1, const float* __restrict__ b2)
{
    int idx = blockIdx.x * blockDim.x + threadIdx.x;   // exactly L*ROWS*INW threads
    int l   = idx >> 19;                               // / (ROWS*INW) = / 2^19
    int rem = idx & 524287;
    int r   = rem >> 9;                                // / INW
    int i   = rem & 511;
    int h   = r >> 1;
    int g   = (r & 1) + 1;                             // original gate (1=z, 2=n)

    float w1  = W1 [l*3 + g];
    float dw1 = dW1[l*3 + g];
    float u1  = U1 [l*3 + g];
    float du1 = dU1[l*3 + g];
    int src = (l*HS + h)*INW + i;                      // INW == HS, same for U2
    g_WG[idx] = w1*W2[src] + dw1*dW2[src];
    g_UG[idx] = u1*U2[src] + du1*dU2[src];

    if (idx < L_NUM*ROWS) {
        int ll = idx >> 10;
        int rr = idx & 1023;
        int hh = rr >> 1;
        int gg = (rr & 1) + 1;
        int bi = ll*3*HS + gg*HS + hh;
        g_bias[idx] = b1[bi] + b2[bi];
    }
}

// ---------------------------------------------------------------------------
// Init: h0 (L,B,HS) -> Hbuf[0][l][h][b];  reset grid-barrier counter
// ---------------------------------------------------------------------------
__global__ void init_h_kernel(const float* __restrict__ h0)
{
    int idx = blockIdx.x * blockDim.x + threadIdx.x;   // 65536 threads
    if (idx == 0) g_arrive = 0ULL;
    int l = idx >> 15;                                 // / (B*HS)
    int rem = idx & 32767;
    int b = rem >> 9;
    int h = rem & 511;
    g_Hbuf[(l*HS + h)*BB + b] = h0[idx];
}

// ---------------------------------------------------------------------------
// Kernel B: fp32 tiled GEMM,  Gx[t][l][r][b] = WG[l][r][:]·x[b][t][:] + bias
//   grid (t=1024, mtile=8, l=2); 128-row x 64-batch tile; 256 thr, 8x4/thread
// ---------------------------------------------------------------------------
__global__ void __launch_bounds__(256) gemm_x_kernel(const float* __restrict__ x)
{
    int t  = blockIdx.x;
    int r0 = blockIdx.y * 128;
    int l  = blockIdx.z;

    __shared__ __align__(16) float As[16][132];   // [kk][m], 132: rows stay 16B-aligned
    __shared__ __align__(16) float Bs[16][68];    // [kk][b]

    int tid = threadIdx.x;
    int tx = tid & 15;             // batch direction
    int ty = tid >> 4;             // row direction
    int m0 = ty * 8;
    int n0 = tx * 4;

    const float* wg = g_WG + ((size_t)l*ROWS + r0) * INW;
    const float* xb = x + (size_t)t * INW;

    float acc[8][4];
    #pragma unroll
    for (int i = 0; i < 8; ++i)
        #pragma unroll
        for (int j = 0; j < 4; ++j) acc[i][j] = 0.0f;

    for (int k0 = 0; k0 < INW; k0 += 16) {
        #pragma unroll
        for (int q = 0; q < 2; ++q) {              // A tile: 128 x 16
            int id = tid + q*256;
            int m  = id >> 2;
            int iq = id & 3;
            float4 v = *(const float4*)(wg + (size_t)m*INW + k0 + iq*4);
            As[iq*4+0][m] = v.x; As[iq*4+1][m] = v.y;
            As[iq*4+2][m] = v.z; As[iq*4+3][m] = v.w;
        }
        {                                          // B tile: 16 x 64
            int b  = tid >> 2;
            int iq = tid & 3;
            float4 v = *(const float4*)(xb + (size_t)b*SS*INW + k0 + iq*4);
            Bs[iq*4+0][b] = v.x; Bs[iq*4+1][b] = v.y;
            Bs[iq*4+2][b] = v.z; Bs[iq*4+3][b] = v.w;
        }
        __syncthreads();
        #pragma unroll
        for (int kk = 0; kk < 16; ++kk) {
            float a[8], bv[4];
            *(float4*)(a)   = *(const float4*)&As[kk][m0];
            *(float4*)(a+4) = *(const float4*)&As[kk][m0+4];
            *(float4*)(bv)  = *(const float4*)&Bs[kk][n0];
            #pragma unroll
            for (int i = 0; i < 8; ++i)
                #pragma unroll
                for (int j = 0; j < 4; ++j)
                    acc[i][j] += a[i] * bv[j];
        }
        __syncthreads();
    }

    float* gout = g_Gx + (((size_t)t*L_NUM + l)*ROWS + r0) * BB;
    #pragma unroll
    for (int i = 0; i < 8; ++i) {
        float bia = g_bias[l*ROWS + r0 + m0 + i];
        float4 v = make_float4(acc[i][0]+bia, acc[i][1]+bia, acc[i][2]+bia, acc[i][3]+bia);
        *(float4*)(gout + (size_t)(m0+i)*BB + n0) = v;
    }
}

// ---------------------------------------------------------------------------
// Kernel C: persistent sequential scan. 128 CTAs x 256 thr, grid barrier/step.
//   CTA: layer l = blockIdx.x>>6, rows r0 = (blockIdx.x&63)*16 (=> h0 = r0/2).
//   UG tile (16x512 = 32 KB) persists in SMEM. Per step: H streamed in 8
//   chunks of 64 o (16 KB), o-split-4 dot with 4r x 4b register tiles, SMEM
//   reduction, activation + ping-pong H update.
// ---------------------------------------------------------------------------
__global__ void __launch_bounds__(256, 1) step_kernel(float* __restrict__ out)
{
    const int tid = threadIdx.x;
    const int l   = blockIdx.x >> 6;
    const int r0  = (blockIdx.x & 63) * 16;
    const int h0  = r0 >> 1;

    __shared__ __align__(16) float UGs[16*512];   // 32 KB, persists whole kernel
    __shared__ __align__(16) float Hs[64*64];     // 16 KB, H chunk / reduction buffer

    {   // load UG tile once
        const float4* src = (const float4*)(g_UG + ((size_t)l*ROWS + r0)*HS);
        float4* dst = (float4*)UGs;
        #pragma unroll
        for (int q = 0; q < 8; ++q) dst[tid + q*256] = src[tid + q*256];
    }

    const int oq = tid >> 6;          // o-split group (0..3)
    const int rg = (tid >> 4) & 3;    // row group (4 rows each)
    const int bg = tid & 15;          // batch group (4 b each)

    float* outSeq   = out;
    float* outState = out + (size_t)SEQ_ELEMS;

    int p = 0;
    for (int t = 0; t < SS; ++t) {
        const float* Hrd = g_Hbuf + (size_t)(p*L_NUM + l)*HS*BB;
        float*       Hwr = g_Hbuf + (size_t)((1-p)*L_NUM + l)*HS*BB;

        float acc[4][4];
        #pragma unroll
        for (int j = 0; j < 4; ++j)
            #pragma unroll
            for (int i = 0; i < 4; ++i) acc[j][i] = 0.0f;

        for (int c = 0; c < 8; ++c) {
            __syncthreads();          // Hs free (prev phase readers done)
            {   // load H chunk: o in [c*64, c*64+64), layout Hs[o_local][b]
                const float4* src = (const float4*)(Hrd + c*64*BB);
                float4* dst = (float4*)Hs;
                #pragma unroll
                for (int q = 0; q < 4; ++q) {
                    int i4 = tid + q*256;
                    dst[i4] = __ldcg(&src[i4]);
                }
            }
            __syncthreads();
            #pragma unroll
            for (int k4 = 0; k4 < 4; ++k4) {
                int ob = oq*16 + k4*4;              // local o base
                float4 h4[4], ug[4];
                #pragma unroll
                for (int oo = 0; oo < 4; ++oo)
                    h4[oo] = *(const float4*)&Hs[(ob+oo)*64 + bg*4];
                #pragma unroll
                for (int j = 0; j < 4; ++j)
                    ug[j] = *(const float4*)&UGs[(rg*4+j)*512 + c*64 + ob];
                #pragma unroll
                for (int oo = 0; oo < 4; ++oo) {
                    #pragma unroll
                    for (int j = 0; j < 4; ++j) {
                        float w = ((const float*)&ug[j])[oo];
                        acc[j][0] += w * ((const float*)&h4[oo])[0];
                        acc[j][1] += w * ((const float*)&h4[oo])[1];
                        acc[j][2] += w * ((const float*)&h4[oo])[2];
                        acc[j][3] += w * ((const float*)&h4[oo])[3];
                    }
                }
            }
        }
        __syncthreads();
        // partial store: red[oq][r_local*64 + b]  (reuses Hs)
        #pragma unroll
        for (int j = 0; j < 4; ++j)
            #pragma unroll
            for (int i = 0; i < 4; ++i)
                Hs[oq*1024 + (rg*4+j)*64 + bg*4 + i] = acc[j][i];
        __syncthreads();

        const float* gx = g_Gx + (((size_t)t*L_NUM + l)*ROWS + r0)*BB;
        #pragma unroll
        for (int it = 0; it < 2; ++it) {
            int u  = tid + it*256;    // 512 (hh,b) updates total
            int hh = u & 7;           // local h (0..7)
            int b  = u >> 3;          // batch (0..63)
            int ez = (2*hh)*64 + b;
            int en = ez + 64;
            float gz = Hs[ez] + Hs[1024+ez] + Hs[2048+ez] + Hs[3072+ez]
                     + gx[(2*hh)*BB + b];
            float gn = Hs[en] + Hs[1024+en] + Hs[2048+en] + Hs[3072+en]
                     + gx[(2*hh+1)*BB + b];
            float hold = __ldcg(&Hrd[(h0+hh)*BB + b]);
            float z = 1.0f / (1.0f + __expf(-gz));
            float n = tanhf(gn);
            float hnew = (1.0f - z)*n + z*hold;
            Hwr[(h0+hh)*BB + b] = hnew;
            if (l == 1)
                outSeq[((size_t)b*SS + t)*HS + h0 + hh] = hnew;
            if (t == SS-1)
                outState[((size_t)l*BB + b)*HS + h0 + hh] = hnew;
        }

        // grid barrier (monotonic counter; reset each launch by init kernel)
        __threadfence();
        __syncthreads();
        if (tid == 0) {
            atomicAdd(&g_arrive, 1ULL);
            unsigned long long target = (unsigned long long)(t+1) * NCTA;
            unsigned long long v;
            do {
                asm volatile("ld.global.acquire.gpu.u64 %0, [%1];"
                             : "=l"(v) : "l"(&g_arrive) : "memory");
            } while (v < target);
        }
        __syncthreads();
        p ^= 1;
    }
}

// ---------------------------------------------------------------------------
// Launch: combine -> init (barrier reset + h0) -> x-GEMM -> persistent scan
// ---------------------------------------------------------------------------
extern "C" void kernel_launch(void* const* d_in, const int* in_sizes, int n_in,
                              void* d_out, int out_size)
{
    const float* x   = (const float*)d_in[0];
    const float* h0  = (const float*)d_in[1];
    const float* W1  = (const float*)d_in[2];
    const float* W2  = (const float*)d_in[3];
    const float* U1  = (const float*)d_in[4];
    const float* U2  = (const float*)d_in[5];
    const float* dW1 = (const float*)d_in[6];
    const float* dW2 = (const float*)d_in[7];
    const float* dU1 = (const float*)d_in[8];
    const float* dU2 = (const float*)d_in[9];
    const float* b1  = (const float*)d_in[10];
    const float* b2  = (const float*)d_in[11];
    float* out = (float*)d_out;

    combine_kernel<<<4096, 256>>>(W1, W2, U1, U2, dW1, dW2, dU1, dU2, b1, b2);
    init_h_kernel<<<256, 256>>>(h0);
    dim3 gg(1024, 8, 2);
    gemm_x_kernel<<<gg, 256>>>(x);
    step_kernel<<<NCTA, 256>>>(out);
    (void)in_sizes; (void)n_in; (void)out_size;
}